// round 5
// baseline (speedup 1.0000x reference)
#include <cuda_runtime.h>
#include <cuda_bf16.h>
#include <cstdint>

// Problem constants (shapes fixed by the dataset)
#define MAXN 100000
#define F_IN 512
#define H1   256
#define H2   128
#define NCLS 4

// Scratch buffers: __device__ globals, float4-typed for 16B alignment.
__device__ float4 g_h1  [(size_t)MAXN * H1 / 4];
__device__ float4 g_agg1[(size_t)MAXN * H1 / 4];
__device__ float4 g_h2  [(size_t)MAXN * H2 / 4];
__device__ float4 g_agg2[(size_t)MAXN * H2 / 4];
__device__ float  g_deg [MAXN];
__device__ float  g_dinv[MAXN];
__device__ int    g_is64;   // 1 if edge_index is int64, 0 if int32

// Buffer-id -> device pointer resolution (done on-device; host-side symbol
// lookup proved unreliable in this harness)
#define BUF_H1   0
#define BUF_AGG1 1
#define BUF_H2   2
#define BUF_AGG2 3

__device__ __forceinline__ float* get_buf(int id) {
    switch (id) {
        case BUF_H1:   return reinterpret_cast<float*>(g_h1);
        case BUF_AGG1: return reinterpret_cast<float*>(g_agg1);
        case BUF_H2:   return reinterpret_cast<float*>(g_h2);
        default:       return reinterpret_cast<float*>(g_agg2);
    }
}

// Load edge index element at logical position pos (0..2E-1), dtype-agnostic.
__device__ __forceinline__ int load_idx(const void* ei, long long pos) {
    if (g_is64) return (int)(reinterpret_cast<const long long*>(ei)[pos]);
    return reinterpret_cast<const int*>(ei)[pos];
}

// ---------------------------------------------------------------------------
// Dtype detection: if edge_index is int64 (values < 2^31), every odd 32-bit
// word is 0. Sample up to 4096 odd words; any nonzero => int32.
// ---------------------------------------------------------------------------
__global__ void k_detect_init() { g_is64 = 1; }

__global__ void k_detect(const int* __restrict__ ei_words, int E2) {
    int i = blockIdx.x * blockDim.x + threadIdx.x;   // sample index
    if (i >= 4096) return;
    long long w = 2LL * i + 1;                        // odd word position
    if (w < E2 && ei_words[w] != 0) g_is64 = 0;       // racy but idempotent
}

// ---------------------------------------------------------------------------
// Degree kernels
// ---------------------------------------------------------------------------
__global__ void k_init_deg(int N) {
    int i = blockIdx.x * blockDim.x + threadIdx.x;
    if (i < N) g_deg[i] = 1.0f;  // self loop
}

__global__ void k_count_deg(const void* __restrict__ ei, int E, int N) {
    int e = blockIdx.x * blockDim.x + threadIdx.x;
    if (e < E) {
        int d = load_idx(ei, (long long)E + e);       // dst[e]
        if ((unsigned)d < (unsigned)N) atomicAdd(&g_deg[d], 1.0f);
    }
}

__global__ void k_dinv(int N) {
    int i = blockIdx.x * blockDim.x + threadIdx.x;
    if (i < N) g_dinv[i] = rsqrtf(g_deg[i]);
}

// ---------------------------------------------------------------------------
// Tiled fp32 GEMM: C[N,M] = A[N,K] @ B[K,M]
// BM=64, BN=64, BK=16, 256 threads, 4x4 micro-tile per thread.
// ---------------------------------------------------------------------------
template <int BM, int BN, int BK>
__global__ void __launch_bounds__(256) k_gemm(const float* __restrict__ Aext,
                                              int a_id,
                                              const float* __restrict__ B,
                                              int c_id,
                                              int Nrows, int K, int M) {
    const float* A = (a_id < 0) ? Aext : get_buf(a_id);
    float*       C = get_buf(c_id);

    __shared__ float As[BK][BM];
    __shared__ float Bs[BK][BN];

    const int tid  = threadIdx.x;          // 0..255
    const int tx   = tid & 15;             // 0..15
    const int ty   = tid >> 4;             // 0..15
    const int row0 = blockIdx.y * BM;
    const int col0 = blockIdx.x * BN;

    float acc[4][4] = {};

    for (int k0 = 0; k0 < K; k0 += BK) {
        {
            const int r  = tid >> 2;            // 0..63 row within tile
            const int kb = (tid & 3) << 2;      // 0,4,8,12
            float4 v = make_float4(0.f, 0.f, 0.f, 0.f);
            const int gr = row0 + r;
            if (gr < Nrows)
                v = *reinterpret_cast<const float4*>(&A[(size_t)gr * K + k0 + kb]);
            As[kb + 0][r] = v.x;
            As[kb + 1][r] = v.y;
            As[kb + 2][r] = v.z;
            As[kb + 3][r] = v.w;
        }
        {
            const int kk = tid >> 4;            // 0..15
            const int cb = (tid & 15) << 2;     // 0,4,...,60
            float4 v = *reinterpret_cast<const float4*>(&B[(size_t)(k0 + kk) * M + col0 + cb]);
            *reinterpret_cast<float4*>(&Bs[kk][cb]) = v;
        }
        __syncthreads();

        #pragma unroll
        for (int kk = 0; kk < BK; kk++) {
            float4 a = *reinterpret_cast<const float4*>(&As[kk][ty * 4]);
            float4 b = *reinterpret_cast<const float4*>(&Bs[kk][tx * 4]);
            float av[4] = {a.x, a.y, a.z, a.w};
            float bv[4] = {b.x, b.y, b.z, b.w};
            #pragma unroll
            for (int i = 0; i < 4; i++)
                #pragma unroll
                for (int j = 0; j < 4; j++)
                    acc[i][j] = fmaf(av[i], bv[j], acc[i][j]);
        }
        __syncthreads();
    }

    #pragma unroll
    for (int i = 0; i < 4; i++) {
        const int gr = row0 + ty * 4 + i;
        if (gr < Nrows) {
            float4 v = make_float4(acc[i][0], acc[i][1], acc[i][2], acc[i][3]);
            *reinterpret_cast<float4*>(&C[(size_t)gr * M + col0 + tx * 4]) = v;
        }
    }
}

// ---------------------------------------------------------------------------
// Self-loop init: out[i][j] = h[i][j] * dinv[i]^2
// ---------------------------------------------------------------------------
template <int H>
__global__ void k_self_init(int h_id, int out_id, int N) {
    const float4* h   = reinterpret_cast<const float4*>(get_buf(h_id));
    float4*       out = reinterpret_cast<float4*>(get_buf(out_id));
    const int nv = N * (H / 4);
    int i4 = blockIdx.x * blockDim.x + threadIdx.x;
    if (i4 >= nv) return;
    const int node = i4 / (H / 4);
    const float di = g_dinv[node];
    const float s  = di * di;
    float4 v = h[i4];
    v.x *= s; v.y *= s; v.z *= s; v.w *= s;
    out[i4] = v;
}

// ---------------------------------------------------------------------------
// Edge aggregation: out[dst] += h[src] * (dinv[src]*dinv[dst])
// One warp per edge, float4 gather + scalar RED.E.ADD.F32 scatter.
// ---------------------------------------------------------------------------
template <int H>
__global__ void __launch_bounds__(256) k_agg(int h_id, int out_id,
                                             const void* __restrict__ ei,
                                             int E, int N) {
    const float* h   = get_buf(h_id);
    float*       out = get_buf(out_id);

    const int warp = (int)((blockIdx.x * (unsigned)blockDim.x + threadIdx.x) >> 5);
    const int lane = threadIdx.x & 31;
    if (warp >= E) return;

    const int s = load_idx(ei, warp);                   // src[e]
    const int d = load_idx(ei, (long long)E + warp);    // dst[e]
    if ((unsigned)s >= (unsigned)N || (unsigned)d >= (unsigned)N) return;
    const float nrm = g_dinv[s] * g_dinv[d];

    const float4* hrow = reinterpret_cast<const float4*>(h + (size_t)s * H);
    float* orow = out + (size_t)d * H;

    #pragma unroll
    for (int t = 0; t < H / 128; t++) {
        const int c = lane + t * 32;          // float4 index within row
        float4 v = hrow[c];
        float* p = orow + c * 4;
        atomicAdd(p + 0, v.x * nrm);
        atomicAdd(p + 1, v.y * nrm);
        atomicAdd(p + 2, v.z * nrm);
        atomicAdd(p + 3, v.w * nrm);
    }
}

// ---------------------------------------------------------------------------
// Bias + ReLU
// ---------------------------------------------------------------------------
template <int H>
__global__ void k_bias_relu(int out_id, const float* __restrict__ b, int N) {
    float4* out = reinterpret_cast<float4*>(get_buf(out_id));
    const int nv = N * (H / 4);
    int i4 = blockIdx.x * blockDim.x + threadIdx.x;
    if (i4 >= nv) return;
    const int j4 = i4 % (H / 4);
    float4 bb = reinterpret_cast<const float4*>(b)[j4];
    float4 v  = out[i4];
    v.x = fmaxf(v.x + bb.x, 0.f);
    v.y = fmaxf(v.y + bb.y, 0.f);
    v.z = fmaxf(v.z + bb.z, 0.f);
    v.w = fmaxf(v.w + bb.w, 0.f);
    out[i4] = v;
}

// ---------------------------------------------------------------------------
// Final: logits = h @ Wl + bl, log_softmax over NCLS=4. One warp per node.
// ---------------------------------------------------------------------------
__global__ void __launch_bounds__(256) k_final(int h_id,
                                               const float* __restrict__ Wl,
                                               const float* __restrict__ bl,
                                               float* __restrict__ out, int N) {
    const float* h = get_buf(h_id);
    const int warp = (int)((blockIdx.x * (unsigned)blockDim.x + threadIdx.x) >> 5);
    const int lane = threadIdx.x & 31;
    if (warp >= N) return;

    float acc0 = 0.f, acc1 = 0.f, acc2 = 0.f, acc3 = 0.f;
    #pragma unroll
    for (int t = 0; t < H2 / 32; t++) {
        const int j = lane + t * 32;
        const float hv = h[(size_t)warp * H2 + j];
        const float4 w = reinterpret_cast<const float4*>(Wl)[j];
        acc0 = fmaf(hv, w.x, acc0);
        acc1 = fmaf(hv, w.y, acc1);
        acc2 = fmaf(hv, w.z, acc2);
        acc3 = fmaf(hv, w.w, acc3);
    }
    #pragma unroll
    for (int off = 16; off > 0; off >>= 1) {
        acc0 += __shfl_xor_sync(0xffffffffu, acc0, off);
        acc1 += __shfl_xor_sync(0xffffffffu, acc1, off);
        acc2 += __shfl_xor_sync(0xffffffffu, acc2, off);
        acc3 += __shfl_xor_sync(0xffffffffu, acc3, off);
    }
    if (lane == 0) {
        float l0 = acc0 + bl[0];
        float l1 = acc1 + bl[1];
        float l2 = acc2 + bl[2];
        float l3 = acc3 + bl[3];
        float m = fmaxf(fmaxf(l0, l1), fmaxf(l2, l3));
        float e0 = __expf(l0 - m), e1 = __expf(l1 - m),
              e2 = __expf(l2 - m), e3 = __expf(l3 - m);
        float lse = logf(e0 + e1 + e2 + e3);
        float4 r = make_float4(l0 - m - lse, l1 - m - lse, l2 - m - lse, l3 - m - lse);
        *reinterpret_cast<float4*>(&out[(size_t)warp * NCLS]) = r;
    }
}

// ---------------------------------------------------------------------------
// Launch
// ---------------------------------------------------------------------------
extern "C" void kernel_launch(void* const* d_in, const int* in_sizes, int n_in,
                              void* d_out, int out_size) {
    const float* x   = (const float*)d_in[0];
    const void*  ei  = d_in[1];
    const float* W1  = (const float*)d_in[2];
    const float* b1  = (const float*)d_in[3];
    const float* W2  = (const float*)d_in[4];
    const float* b2  = (const float*)d_in[5];
    const float* Wl  = (const float*)d_in[6];
    const float* bl  = (const float*)d_in[7];
    float*       out = (float*)d_out;

    const int N = in_sizes[0] / F_IN;
    const int E = in_sizes[1] / 2;

    const int T = 256;

    // Detect edge_index dtype (int32 vs int64)
    k_detect_init<<<1, 1>>>();
    k_detect<<<(4096 + T - 1) / T, T>>>((const int*)ei, 2 * E);

    // Degrees + normalization
    k_init_deg<<<(N + T - 1) / T, T>>>(N);
    k_count_deg<<<(E + T - 1) / T, T>>>(ei, E, N);
    k_dinv<<<(N + T - 1) / T, T>>>(N);

    // Layer 1: h1 = x @ W1
    {
        dim3 grid(H1 / 64, (N + 63) / 64);
        k_gemm<64, 64, 16><<<grid, 256>>>(x, -1, W1, BUF_H1, N, F_IN, H1);
    }
    k_self_init<H1><<<(N * (H1 / 4) + T - 1) / T, T>>>(BUF_H1, BUF_AGG1, N);
    k_agg<H1><<<(int)(((long long)E * 32 + T - 1) / T), T>>>(BUF_H1, BUF_AGG1, ei, E, N);
    k_bias_relu<H1><<<(N * (H1 / 4) + T - 1) / T, T>>>(BUF_AGG1, b1, N);

    // Layer 2: h2 = relu1 @ W2
    {
        dim3 grid(H2 / 64, (N + 63) / 64);
        k_gemm<64, 64, 16><<<grid, 256>>>(nullptr, BUF_AGG1, W2, BUF_H2, N, H1, H2);
    }
    k_self_init<H2><<<(N * (H2 / 4) + T - 1) / T, T>>>(BUF_H2, BUF_AGG2, N);
    k_agg<H2><<<(int)(((long long)E * 32 + T - 1) / T), T>>>(BUF_H2, BUF_AGG2, ei, E, N);
    k_bias_relu<H2><<<(N * (H2 / 4) + T - 1) / T, T>>>(BUF_AGG2, b2, N);

    // Logits + log_softmax
    k_final<<<(N * 32 + T - 1) / T, T>>>(BUF_AGG2, Wl, bl, out, N);
}

// round 7
// speedup vs baseline: 2.8925x; 2.8925x over previous
#include <cuda_runtime.h>
#include <cuda_bf16.h>
#include <cstdint>

// Problem constants (shapes fixed by the dataset)
#define MAXN 100000
#define MAXE 3400000
#define F_IN 512
#define H1   256
#define H2   128
#define NCLS 4
#define NB_SCAN ((MAXN + 255) / 256)

// Scratch buffers: __device__ globals, float4-typed for 16B alignment.
__device__ float4 g_h1  [(size_t)MAXN * H1 / 4];
__device__ float4 g_agg1[(size_t)MAXN * H1 / 4];
__device__ float4 g_h2  [(size_t)MAXN * H2 / 4];
__device__ float  g_dinv[MAXN];
__device__ int    g_is64;   // 1 if edge_index is int64, 0 if int32

// CSR structures (rebuilt every call; deterministic up to neighbor order)
__device__ int g_csr_src[MAXE];
__device__ int g_row_ptr[MAXN + 1];
__device__ int g_row_cnt[MAXN];          // histogram, then scatter cursor
__device__ int g_blocksum[NB_SCAN + 1];

// Buffer-id -> device pointer resolution (host-side symbol lookup is
// unreliable in this harness; resolve on-device)
#define BUF_H1   0
#define BUF_AGG1 1
#define BUF_H2   2

__device__ __forceinline__ float* get_buf(int id) {
    switch (id) {
        case BUF_H1:   return reinterpret_cast<float*>(g_h1);
        case BUF_AGG1: return reinterpret_cast<float*>(g_agg1);
        default:       return reinterpret_cast<float*>(g_h2);
    }
}

// Load edge index element at logical position pos (0..2E-1), dtype-agnostic.
__device__ __forceinline__ int load_idx(const void* ei, long long pos) {
    if (g_is64) return (int)(reinterpret_cast<const long long*>(ei)[pos]);
    return reinterpret_cast<const int*>(ei)[pos];
}

// ---------------------------------------------------------------------------
// Dtype detection: int64 indices < 2^31 have all-zero odd 32-bit words.
// ---------------------------------------------------------------------------
__global__ void k_detect_init() { g_is64 = 1; }

__global__ void k_detect(const int* __restrict__ ei_words, int E2) {
    int i = blockIdx.x * blockDim.x + threadIdx.x;
    if (i >= 4096) return;
    long long w = 2LL * i + 1;
    if (w < E2 && ei_words[w] != 0) g_is64 = 0;
}

// ---------------------------------------------------------------------------
// CSR build: histogram -> exclusive scan -> scatter
// ---------------------------------------------------------------------------
__global__ void k_zero_cnt(int N) {
    int i = blockIdx.x * blockDim.x + threadIdx.x;
    if (i < N) g_row_cnt[i] = 0;
}

__global__ void k_hist(const void* __restrict__ ei, int E, int N) {
    int e = blockIdx.x * blockDim.x + threadIdx.x;
    if (e < E) {
        int d = load_idx(ei, (long long)E + e);
        if ((unsigned)d < (unsigned)N) atomicAdd(&g_row_cnt[d], 1);
    }
}

__global__ void k_dinv(int N) {
    int i = blockIdx.x * blockDim.x + threadIdx.x;
    if (i < N) g_dinv[i] = rsqrtf((float)g_row_cnt[i] + 1.0f);  // +1 self loop
}

// Per-block exclusive scan; block totals to g_blocksum.
__global__ void k_scan1(int N) {
    __shared__ int sh[256];
    const int t = threadIdx.x;
    const int i = blockIdx.x * 256 + t;
    int v = (i < N) ? g_row_cnt[i] : 0;
    sh[t] = v;
    __syncthreads();
    #pragma unroll
    for (int off = 1; off < 256; off <<= 1) {
        int x = (t >= off) ? sh[t - off] : 0;
        __syncthreads();
        sh[t] += x;
        __syncthreads();
    }
    if (i < N) g_row_ptr[i] = sh[t] - v;            // exclusive within block
    if (t == 255) g_blocksum[blockIdx.x] = sh[255]; // block total
}

// Scan block sums (nb <= 1024) in a single block.
__global__ void k_scan2(int nb) {
    __shared__ int sh[1024];
    const int t = threadIdx.x;
    int v = (t < nb) ? g_blocksum[t] : 0;
    sh[t] = v;
    __syncthreads();
    #pragma unroll
    for (int off = 1; off < 1024; off <<= 1) {
        int x = (t >= off) ? sh[t - off] : 0;
        __syncthreads();
        sh[t] += x;
        __syncthreads();
    }
    if (t < nb) g_blocksum[t] = sh[t] - v;          // exclusive
}

// Add block offsets; set row_ptr[N].
__global__ void k_scan3(int N) {
    const int i = blockIdx.x * 256 + threadIdx.x;
    if (i < N) {
        g_row_ptr[i] += g_blocksum[i >> 8];
        if (i == N - 1) g_row_ptr[N] = g_row_ptr[i] + g_row_cnt[i];
    }
}

__global__ void k_scatter(const void* __restrict__ ei, int E, int N) {
    int e = blockIdx.x * blockDim.x + threadIdx.x;
    if (e >= E) return;
    int s = load_idx(ei, e);
    int d = load_idx(ei, (long long)E + e);
    if ((unsigned)s >= (unsigned)N || (unsigned)d >= (unsigned)N) return;
    int pos = g_row_ptr[d] + atomicAdd(&g_row_cnt[d], 1);
    if (pos < MAXE) g_csr_src[pos] = s;
}

// ---------------------------------------------------------------------------
// Tiled fp32 GEMM: C[N,M] = A[N,K] @ B[K,M]
// ---------------------------------------------------------------------------
template <int BM, int BN, int BK>
__global__ void __launch_bounds__(256) k_gemm(const float* __restrict__ Aext,
                                              int a_id,
                                              const float* __restrict__ B,
                                              int c_id,
                                              int Nrows, int K, int M) {
    const float* A = (a_id < 0) ? Aext : get_buf(a_id);
    float*       C = get_buf(c_id);

    __shared__ float As[BK][BM];
    __shared__ float Bs[BK][BN];

    const int tid  = threadIdx.x;
    const int tx   = tid & 15;
    const int ty   = tid >> 4;
    const int row0 = blockIdx.y * BM;
    const int col0 = blockIdx.x * BN;

    float acc[4][4] = {};

    for (int k0 = 0; k0 < K; k0 += BK) {
        {
            const int r  = tid >> 2;
            const int kb = (tid & 3) << 2;
            float4 v = make_float4(0.f, 0.f, 0.f, 0.f);
            const int gr = row0 + r;
            if (gr < Nrows)
                v = *reinterpret_cast<const float4*>(&A[(size_t)gr * K + k0 + kb]);
            As[kb + 0][r] = v.x;
            As[kb + 1][r] = v.y;
            As[kb + 2][r] = v.z;
            As[kb + 3][r] = v.w;
        }
        {
            const int kk = tid >> 4;
            const int cb = (tid & 15) << 2;
            float4 v = *reinterpret_cast<const float4*>(&B[(size_t)(k0 + kk) * M + col0 + cb]);
            *reinterpret_cast<float4*>(&Bs[kk][cb]) = v;
        }
        __syncthreads();

        #pragma unroll
        for (int kk = 0; kk < BK; kk++) {
            float4 a = *reinterpret_cast<const float4*>(&As[kk][ty * 4]);
            float4 b = *reinterpret_cast<const float4*>(&Bs[kk][tx * 4]);
            float av[4] = {a.x, a.y, a.z, a.w};
            float bv[4] = {b.x, b.y, b.z, b.w};
            #pragma unroll
            for (int i = 0; i < 4; i++)
                #pragma unroll
                for (int j = 0; j < 4; j++)
                    acc[i][j] = fmaf(av[i], bv[j], acc[i][j]);
        }
        __syncthreads();
    }

    #pragma unroll
    for (int i = 0; i < 4; i++) {
        const int gr = row0 + ty * 4 + i;
        if (gr < Nrows) {
            float4 v = make_float4(acc[i][0], acc[i][1], acc[i][2], acc[i][3]);
            *reinterpret_cast<float4*>(&C[(size_t)gr * M + col0 + tx * 4]) = v;
        }
    }
}

// ---------------------------------------------------------------------------
// CSR aggregation, one warp per dst node, fused self-loop + bias + ReLU:
//   out[d] = relu( dd * ( dd*h[d] + sum_s dinv[s]*h[s] ) + bias )
// ---------------------------------------------------------------------------
template <int H>
__global__ void __launch_bounds__(256) k_agg_csr(int h_id, int out_id,
                                                 const float* __restrict__ bias,
                                                 int N) {
    const float* h   = get_buf(h_id);
    float*       out = get_buf(out_id);

    const int d    = (int)((blockIdx.x * (unsigned)blockDim.x + threadIdx.x) >> 5);
    const int lane = threadIdx.x & 31;
    if (d >= N) return;

    constexpr int C = H / 128;             // float4s per lane (H1:2, H2:1)
    const float dd = g_dinv[d];

    float4 acc[C];
    {
        const float4* hd = reinterpret_cast<const float4*>(h + (size_t)d * H);
        #pragma unroll
        for (int c = 0; c < C; c++) {
            float4 v = hd[lane + 32 * c];
            acc[c] = make_float4(v.x * dd, v.y * dd, v.z * dd, v.w * dd);
        }
    }

    const int beg = g_row_ptr[d];
    const int end = g_row_ptr[d + 1];

    for (int j0 = beg; j0 < end; j0 += 32) {
        const int myidx = (j0 + lane < end) ? g_csr_src[j0 + lane] : 0;
        const int cnt   = min(32, end - j0);
        for (int k = 0; k < cnt; k++) {
            const int   s = __shfl_sync(0xffffffffu, myidx, k);
            const float w = g_dinv[s];
            const float4* hs = reinterpret_cast<const float4*>(h + (size_t)s * H);
            #pragma unroll
            for (int c = 0; c < C; c++) {
                float4 v = hs[lane + 32 * c];
                acc[c].x = fmaf(v.x, w, acc[c].x);
                acc[c].y = fmaf(v.y, w, acc[c].y);
                acc[c].z = fmaf(v.z, w, acc[c].z);
                acc[c].w = fmaf(v.w, w, acc[c].w);
            }
        }
    }

    const float4* bb = reinterpret_cast<const float4*>(bias);
    #pragma unroll
    for (int c = 0; c < C; c++) {
        float4 b = bb[lane + 32 * c];
        float4 r;
        r.x = fmaxf(fmaf(acc[c].x, dd, b.x), 0.f);
        r.y = fmaxf(fmaf(acc[c].y, dd, b.y), 0.f);
        r.z = fmaxf(fmaf(acc[c].z, dd, b.z), 0.f);
        r.w = fmaxf(fmaf(acc[c].w, dd, b.w), 0.f);
        reinterpret_cast<float4*>(out + (size_t)d * H)[lane + 32 * c] = r;
    }
}

// ---------------------------------------------------------------------------
// Layer-2 aggregation fused with logits + log_softmax.
// Warp per node; each lane holds 4 contiguous H2 columns -> dot with Wl rows,
// shfl-reduce, lane 0 computes log-softmax and writes 4 outputs.
// ---------------------------------------------------------------------------
__global__ void __launch_bounds__(256) k_agg_csr_final(int h_id,
                                                       const float* __restrict__ bias,
                                                       const float* __restrict__ Wl,
                                                       const float* __restrict__ bl,
                                                       float* __restrict__ out,
                                                       int N) {
    const float* h = get_buf(h_id);

    const int d    = (int)((blockIdx.x * (unsigned)blockDim.x + threadIdx.x) >> 5);
    const int lane = threadIdx.x & 31;
    if (d >= N) return;

    const float dd = g_dinv[d];

    float4 acc;
    {
        float4 v = reinterpret_cast<const float4*>(h + (size_t)d * H2)[lane];
        acc = make_float4(v.x * dd, v.y * dd, v.z * dd, v.w * dd);
    }

    const int beg = g_row_ptr[d];
    const int end = g_row_ptr[d + 1];

    for (int j0 = beg; j0 < end; j0 += 32) {
        const int myidx = (j0 + lane < end) ? g_csr_src[j0 + lane] : 0;
        const int cnt   = min(32, end - j0);
        for (int k = 0; k < cnt; k++) {
            const int   s = __shfl_sync(0xffffffffu, myidx, k);
            const float w = g_dinv[s];
            float4 v = reinterpret_cast<const float4*>(h + (size_t)s * H2)[lane];
            acc.x = fmaf(v.x, w, acc.x);
            acc.y = fmaf(v.y, w, acc.y);
            acc.z = fmaf(v.z, w, acc.z);
            acc.w = fmaf(v.w, w, acc.w);
        }
    }

    // bias + relu -> this lane's 4 H2 values (columns 4*lane .. 4*lane+3)
    float4 b = reinterpret_cast<const float4*>(bias)[lane];
    float r0 = fmaxf(fmaf(acc.x, dd, b.x), 0.f);
    float r1 = fmaxf(fmaf(acc.y, dd, b.y), 0.f);
    float r2 = fmaxf(fmaf(acc.z, dd, b.z), 0.f);
    float r3 = fmaxf(fmaf(acc.w, dd, b.w), 0.f);

    // partial logits: Wl row j = 4 contiguous floats
    const float4 w0 = reinterpret_cast<const float4*>(Wl)[lane * 4 + 0];
    const float4 w1 = reinterpret_cast<const float4*>(Wl)[lane * 4 + 1];
    const float4 w2 = reinterpret_cast<const float4*>(Wl)[lane * 4 + 2];
    const float4 w3 = reinterpret_cast<const float4*>(Wl)[lane * 4 + 3];
    float l0 = r0 * w0.x + r1 * w1.x + r2 * w2.x + r3 * w3.x;
    float l1 = r0 * w0.y + r1 * w1.y + r2 * w2.y + r3 * w3.y;
    float l2 = r0 * w0.z + r1 * w1.z + r2 * w2.z + r3 * w3.z;
    float l3 = r0 * w0.w + r1 * w1.w + r2 * w2.w + r3 * w3.w;

    #pragma unroll
    for (int off = 16; off > 0; off >>= 1) {
        l0 += __shfl_xor_sync(0xffffffffu, l0, off);
        l1 += __shfl_xor_sync(0xffffffffu, l1, off);
        l2 += __shfl_xor_sync(0xffffffffu, l2, off);
        l3 += __shfl_xor_sync(0xffffffffu, l3, off);
    }

    if (lane == 0) {
        l0 += bl[0]; l1 += bl[1]; l2 += bl[2]; l3 += bl[3];
        float m = fmaxf(fmaxf(l0, l1), fmaxf(l2, l3));
        float e0 = __expf(l0 - m), e1 = __expf(l1 - m),
              e2 = __expf(l2 - m), e3 = __expf(l3 - m);
        float lse = logf(e0 + e1 + e2 + e3);
        float4 r = make_float4(l0 - m - lse, l1 - m - lse, l2 - m - lse, l3 - m - lse);
        *reinterpret_cast<float4*>(&out[(size_t)d * NCLS]) = r;
    }
}

// ---------------------------------------------------------------------------
// Launch
// ---------------------------------------------------------------------------
extern "C" void kernel_launch(void* const* d_in, const int* in_sizes, int n_in,
                              void* d_out, int out_size) {
    const float* x   = (const float*)d_in[0];
    const void*  ei  = d_in[1];
    const float* W1  = (const float*)d_in[2];
    const float* b1  = (const float*)d_in[3];
    const float* W2  = (const float*)d_in[4];
    const float* b2  = (const float*)d_in[5];
    const float* Wl  = (const float*)d_in[6];
    const float* bl  = (const float*)d_in[7];
    float*       out = (float*)d_out;

    const int N = in_sizes[0] / F_IN;
    const int E = in_sizes[1] / 2;
    const int T = 256;
    const int nb = (N + 255) / 256;

    // Detect edge_index dtype (int32 vs int64)
    k_detect_init<<<1, 1>>>();
    k_detect<<<(4096 + T - 1) / T, T>>>((const int*)ei, 2 * E);

    // CSR build + degree normalization
    k_zero_cnt<<<nb, T>>>(N);
    k_hist<<<(E + T - 1) / T, T>>>(ei, E, N);
    k_dinv<<<nb, T>>>(N);
    k_scan1<<<nb, T>>>(N);
    k_scan2<<<1, 1024>>>(nb);
    k_scan3<<<nb, T>>>(N);
    k_zero_cnt<<<nb, T>>>(N);
    k_scatter<<<(E + T - 1) / T, T>>>(ei, E, N);

    // Layer 1: h1 = x @ W1; agg fused with self-loop + bias + relu
    {
        dim3 grid(H1 / 64, (N + 63) / 64);
        k_gemm<64, 64, 16><<<grid, 256>>>(x, -1, W1, BUF_H1, N, F_IN, H1);
    }
    k_agg_csr<H1><<<(int)(((long long)N * 32 + T - 1) / T), T>>>(BUF_H1, BUF_AGG1, b1, N);

    // Layer 2: h2 = relu1 @ W2; agg fused with bias + relu + logits + softmax
    {
        dim3 grid(H2 / 64, (N + 63) / 64);
        k_gemm<64, 64, 16><<<grid, 256>>>(nullptr, BUF_AGG1, W2, BUF_H2, N, H1, H2);
    }
    k_agg_csr_final<<<(int)(((long long)N * 32 + T - 1) / T), T>>>(BUF_H2, b2, Wl, bl, out, N);
}